// round 5
// baseline (speedup 1.0000x reference)
#include <cuda_runtime.h>
#include <cuda_fp16.h>

#define B_    4
#define N_    2048
#define F_IN  256
#define H_    8
#define F_OUT 64
#define HF    (H_ * F_OUT)       // 512
#define DEG_CAP 256

// Scratch (device globals: allocation-free per harness rules)
__device__ __half g_h16[(size_t)B_ * N_ * HF];     // [b][n][h][o], fp16
__device__ float  g_atts2[B_ * N_ * H_];           // [b][n][h]
__device__ float  g_attn2[B_ * N_ * H_];           // [b][n][h]
__device__ int    g_deg[B_ * N_];
__device__ int    g_nbr[(size_t)B_ * N_ * DEG_CAP];

// -------------------------------------------------------------------------
// Kernel 1: h = X @ W per head (fp32 accum). 128x64 tile, 8x4 micro-tile.
// Fused epilogue: att logits from fp32 accs (exact) + fp16 h store [b][n][h][o].
// -------------------------------------------------------------------------
__global__ __launch_bounds__(256) void gemm_h_kernel(const float* __restrict__ X,
                                                     const float* __restrict__ W,
                                                     const float* __restrict__ a_self,
                                                     const float* __restrict__ a_neigh) {
    const int head = blockIdx.y;
    const int b    = blockIdx.x >> 4;          // 16 n-tiles of 128 per batch
    const int n0   = (blockIdx.x & 15) * 128;

    __shared__ float Xs[128][20];   // 16-col k-tile, padded stride 20
    __shared__ float Ws[16][64];

    const int t  = threadIdx.x;
    const int ty = t >> 4;          // 0..15 -> rows ty*8..+7
    const int tx = t & 15;          // 0..15 -> cols tx*4..+3

    const float* Xb = X + ((size_t)b * N_ + n0) * F_IN;
    const float* Wh = W + (size_t)head * F_IN * F_OUT;

    float acc[8][4] = {};

    for (int k0 = 0; k0 < F_IN; k0 += 16) {
        {   // load X tile: 128 rows x 16 cols; each thread 8 consecutive floats
            int row = t >> 1;
            int q   = (t & 1) * 8;
            const float* src = Xb + (size_t)row * F_IN + k0 + q;
            float4 v0 = *(const float4*)(src);
            float4 v1 = *(const float4*)(src + 4);
            *(float4*)&Xs[row][q]     = v0;
            *(float4*)&Xs[row][q + 4] = v1;
        }
        {   // load W tile: 16 rows x 64 cols
            int r = t >> 4;
            int q = (t & 15) * 4;
            *(float4*)&Ws[r][q] = *(const float4*)(Wh + (size_t)(k0 + r) * F_OUT + q);
        }
        __syncthreads();

        #pragma unroll
        for (int k = 0; k < 16; k++) {
            float4 bv = *(float4*)&Ws[k][tx * 4];
            float a[8];
            #pragma unroll
            for (int r = 0; r < 8; r++) a[r] = Xs[ty * 8 + r][k];
            #pragma unroll
            for (int r = 0; r < 8; r++) {
                acc[r][0] = fmaf(a[r], bv.x, acc[r][0]);
                acc[r][1] = fmaf(a[r], bv.y, acc[r][1]);
                acc[r][2] = fmaf(a[r], bv.z, acc[r][2]);
                acc[r][3] = fmaf(a[r], bv.w, acc[r][3]);
            }
        }
        __syncthreads();
    }

    // ---- epilogue 1: attention logits from fp32 accumulators ----
    {
        const float* as = a_self  + head * F_OUT;
        const float* an = a_neigh + head * F_OUT;
        float s[8] = {}, nn[8] = {};
        #pragma unroll
        for (int r = 0; r < 8; r++) {
            #pragma unroll
            for (int c = 0; c < 4; c++) {
                s[r]  = fmaf(acc[r][c], as[tx * 4 + c], s[r]);
                nn[r] = fmaf(acc[r][c], an[tx * 4 + c], nn[r]);
            }
        }
        #pragma unroll
        for (int off = 8; off >= 1; off >>= 1) {
            #pragma unroll
            for (int r = 0; r < 8; r++) {
                s[r]  += __shfl_xor_sync(0xFFFFFFFFu, s[r], off);
                nn[r] += __shfl_xor_sync(0xFFFFFFFFu, nn[r], off);
            }
        }
        if (tx == 0) {
            #pragma unroll
            for (int r = 0; r < 8; r++) {
                size_t idx = ((size_t)b * N_ + n0 + ty * 8 + r) * H_ + head;
                g_atts2[idx] = s[r];
                g_attn2[idx] = nn[r];
            }
        }
    }

    // ---- epilogue 2: fp16 h store to [b][n][h][o] ----
    #pragma unroll
    for (int r = 0; r < 8; r++) {
        int n = n0 + ty * 8 + r;
        __half2 p0 = __floats2half2_rn(acc[r][0], acc[r][1]);
        __half2 p1 = __floats2half2_rn(acc[r][2], acc[r][3]);
        __half2* dst = (__half2*)(g_h16 + ((size_t)b * N_ + n) * HF + head * F_OUT + tx * 4);
        dst[0] = p0;
        dst[1] = p1;
    }
}

// -------------------------------------------------------------------------
// Kernel 2: CSR neighbor lists. One warp per (b,i) row; float4 per lane,
// popc + shfl exclusive scan for compaction (128 cols per iteration).
// -------------------------------------------------------------------------
__global__ __launch_bounds__(256) void nbr_kernel(const float* __restrict__ A) {
    int warp = (blockIdx.x * blockDim.x + threadIdx.x) >> 5;
    int lane = threadIdx.x & 31;
    if (warp >= B_ * N_) return;
    const float* row = A + (size_t)warp * N_;
    int* outp = g_nbr + (size_t)warp * DEG_CAP;
    int base = 0;
    for (int c = 0; c < N_; c += 128) {
        float4 v = *(const float4*)(row + c + lane * 4);
        unsigned m4 = (v.x != 0.0f ? 1u : 0u) | (v.y != 0.0f ? 2u : 0u) |
                      (v.z != 0.0f ? 4u : 0u) | (v.w != 0.0f ? 8u : 0u);
        int cnt = __popc(m4);
        // exclusive warp scan of cnt
        int excl = cnt;
        #pragma unroll
        for (int off = 1; off < 32; off <<= 1) {
            int o = __shfl_up_sync(0xFFFFFFFFu, excl, off);
            if (lane >= off) excl += o;
        }
        int total = __shfl_sync(0xFFFFFFFFu, excl, 31);
        excl -= cnt;
        int pos = base + excl;
        int col = c + lane * 4;
        if (m4 & 1u) { if (pos < DEG_CAP) outp[pos] = col;     pos++; }
        if (m4 & 2u) { if (pos < DEG_CAP) outp[pos] = col + 1; pos++; }
        if (m4 & 4u) { if (pos < DEG_CAP) outp[pos] = col + 2; pos++; }
        if (m4 & 8u) { if (pos < DEG_CAP) outp[pos] = col + 3; }
        base += total;
    }
    if (lane == 0) g_deg[warp] = base < DEG_CAP ? base : DEG_CAP;
}

// -------------------------------------------------------------------------
// Kernel 3: sparse gather-aggregate, fp16 payload, 8-deep unroll (MLP=2).
// CTA = (b,i); warp = head. Lane l handles neighbor group l>>3, cols (l&7)*8.
// -------------------------------------------------------------------------
__global__ __launch_bounds__(256) void agg_kernel(float* __restrict__ out) {
    const int bi = blockIdx.x;          // b*N + i
    const int b  = bi >> 11;
    const int t  = threadIdx.x;
    const int h  = t >> 5;
    const int l  = t & 31;

    __shared__ int   idx_s[DEG_CAP];
    __shared__ float w_s[DEG_CAP][8];
    __shared__ float atts_s[8];

    const int deg  = g_deg[bi];
    const int deg8 = (deg + 7) & ~7;

    for (int k = t; k < deg; k += 256) idx_s[k] = g_nbr[(size_t)bi * DEG_CAP + k];
    if (t < 8) atts_s[t] = g_atts2[(size_t)bi * 8 + t];
    __syncthreads();

    // phase 1: weights for all (neighbor, head); pad [deg, deg8) with zeros
    if (t < deg) {
        int j = idx_s[t];
        const float* an = g_attn2 + ((size_t)(b * N_) + j) * 8;
        float4 a0 = *(const float4*)an;
        float4 a1 = *(const float4*)(an + 4);
        float vals[8] = {a0.x, a0.y, a0.z, a0.w, a1.x, a1.y, a1.z, a1.w};
        float w[8];
        #pragma unroll
        for (int hh = 0; hh < 8; hh++) {
            float x  = atts_s[hh] + vals[hh];
            float sc = fmaxf(x, 0.2f * x);
            w[hh] = __expf(sc);
        }
        *(float4*)&w_s[t][0] = make_float4(w[0], w[1], w[2], w[3]);
        *(float4*)&w_s[t][4] = make_float4(w[4], w[5], w[6], w[7]);
    } else if (t < deg8) {
        idx_s[t] = 0;
        *(float4*)&w_s[t][0] = make_float4(0.f, 0.f, 0.f, 0.f);
        *(float4*)&w_s[t][4] = make_float4(0.f, 0.f, 0.f, 0.f);
    }
    __syncthreads();

    // phase 2: gather + weighted sum; 2 independent LDG.128 in flight per lane
    const int grp = l >> 3;
    const int q8  = (l & 7) * 8;     // 8 halves per lane
    const __half* hb = g_h16 + ((size_t)b * N_) * HF + h * F_OUT + q8;

    float acc[8] = {};
    float dacc = 0.f;

    for (int k = 0; k < deg8; k += 8) {
        int   ja = idx_s[k + grp];
        int   jb = idx_s[k + 4 + grp];
        float wa = w_s[k + grp][h];
        float wb = w_s[k + 4 + grp][h];
        uint4 va = *(const uint4*)(hb + (unsigned)ja * HF);
        uint4 vb = *(const uint4*)(hb + (unsigned)jb * HF);

        float2 f0 = __half22float2(*(__half2*)&va.x);
        float2 f1 = __half22float2(*(__half2*)&va.y);
        float2 f2 = __half22float2(*(__half2*)&va.z);
        float2 f3 = __half22float2(*(__half2*)&va.w);
        acc[0] = fmaf(wa, f0.x, acc[0]); acc[1] = fmaf(wa, f0.y, acc[1]);
        acc[2] = fmaf(wa, f1.x, acc[2]); acc[3] = fmaf(wa, f1.y, acc[3]);
        acc[4] = fmaf(wa, f2.x, acc[4]); acc[5] = fmaf(wa, f2.y, acc[5]);
        acc[6] = fmaf(wa, f3.x, acc[6]); acc[7] = fmaf(wa, f3.y, acc[7]);

        float2 g0 = __half22float2(*(__half2*)&vb.x);
        float2 g1 = __half22float2(*(__half2*)&vb.y);
        float2 g2 = __half22float2(*(__half2*)&vb.z);
        float2 g3 = __half22float2(*(__half2*)&vb.w);
        acc[0] = fmaf(wb, g0.x, acc[0]); acc[1] = fmaf(wb, g0.y, acc[1]);
        acc[2] = fmaf(wb, g1.x, acc[2]); acc[3] = fmaf(wb, g1.y, acc[3]);
        acc[4] = fmaf(wb, g2.x, acc[4]); acc[5] = fmaf(wb, g2.y, acc[5]);
        acc[6] = fmaf(wb, g3.x, acc[6]); acc[7] = fmaf(wb, g3.y, acc[7]);

        dacc += wa + wb;
    }

    // combine the 4 neighbor-groups (and denominator) across lanes
    #pragma unroll
    for (int c = 0; c < 8; c++) {
        acc[c] += __shfl_xor_sync(0xFFFFFFFFu, acc[c], 8);
        acc[c] += __shfl_xor_sync(0xFFFFFFFFu, acc[c], 16);
    }
    dacc += __shfl_xor_sync(0xFFFFFFFFu, dacc, 8);
    dacc += __shfl_xor_sync(0xFFFFFFFFu, dacc, 16);

    if (l < 8) {
        float inv = 1.0f / dacc;
        float4 o0, o1;
        o0.x = fmaxf(acc[0] * inv, 0.f); o0.y = fmaxf(acc[1] * inv, 0.f);
        o0.z = fmaxf(acc[2] * inv, 0.f); o0.w = fmaxf(acc[3] * inv, 0.f);
        o1.x = fmaxf(acc[4] * inv, 0.f); o1.y = fmaxf(acc[5] * inv, 0.f);
        o1.z = fmaxf(acc[6] * inv, 0.f); o1.w = fmaxf(acc[7] * inv, 0.f);
        float* op = out + (size_t)bi * HF + h * F_OUT + q8;
        *(float4*)op       = o0;
        *(float4*)(op + 4) = o1;
    }
}

// -------------------------------------------------------------------------
extern "C" void kernel_launch(void* const* d_in, const int* in_sizes, int n_in,
                              void* d_out, int out_size) {
    const float* X       = (const float*)d_in[0];
    const float* A       = (const float*)d_in[1];
    const float* W       = (const float*)d_in[2];
    const float* a_self  = (const float*)d_in[3];
    const float* a_neigh = (const float*)d_in[4];
    float* out = (float*)d_out;

    // 1) adjacency -> CSR neighbor lists
    nbr_kernel<<<(B_ * N_) / 8, 256>>>(A);

    // 2) h = X @ W per head + fused att logits + fp16 h store
    gemm_h_kernel<<<dim3((N_ / 128) * B_, H_), 256>>>(X, W, a_self, a_neigh);

    // 3) sparse masked-softmax aggregation + relu + concat
    agg_kernel<<<B_ * N_, 256>>>(out);
}

// round 6
// speedup vs baseline: 1.0185x; 1.0185x over previous
#include <cuda_runtime.h>
#include <cuda_fp16.h>

#define B_    4
#define N_    2048
#define F_IN  256
#define H_    8
#define F_OUT 64
#define HF    (H_ * F_OUT)       // 512
#define DEG_CAP 256

// Scratch (device globals: allocation-free per harness rules)
__device__ __half g_h16[(size_t)B_ * N_ * HF];     // [b][n][h][o], fp16
__device__ float  g_atts2[B_ * N_ * H_];           // [b][n][h]
__device__ float  g_attn2[B_ * N_ * H_];           // [b][n][h]
__device__ int    g_deg[B_ * N_];
__device__ int    g_nbr[(size_t)B_ * N_ * DEG_CAP];

// -------------------------------------------------------------------------
// Kernel 1: h = X @ W per head (fp32 accum), 64x64 tile, 4x4 micro-tile.
// Fused epilogue: att logits from fp32 accs (exact) + fp16 h store [b][n][h][o].
// (identical to R4 measured-best)
// -------------------------------------------------------------------------
__global__ __launch_bounds__(256) void gemm_h_kernel(const float* __restrict__ X,
                                                     const float* __restrict__ W,
                                                     const float* __restrict__ a_self,
                                                     const float* __restrict__ a_neigh) {
    const int head = blockIdx.y;
    const int b    = blockIdx.x >> 5;
    const int n0   = (blockIdx.x & 31) * 64;

    __shared__ float Xs[64][20];
    __shared__ float Ws[16][64];

    const int t  = threadIdx.x;
    const int ty = t >> 4;
    const int tx = t & 15;

    const float* Xb = X + ((size_t)b * N_ + n0) * F_IN;
    const float* Wh = W + (size_t)head * F_IN * F_OUT;

    float acc[4][4] = {};

    for (int k0 = 0; k0 < F_IN; k0 += 16) {
        {
            int row = t >> 2;
            int q   = (t & 3) * 4;
            float4 v = *(const float4*)(Xb + (size_t)row * F_IN + k0 + q);
            *(float4*)&Xs[row][q] = v;
        }
        {
            int r = t >> 4;
            int q = (t & 15) * 4;
            *(float4*)&Ws[r][q] = *(const float4*)(Wh + (size_t)(k0 + r) * F_OUT + q);
        }
        __syncthreads();

        #pragma unroll
        for (int k = 0; k < 16; k++) {
            float a0 = Xs[ty * 4 + 0][k];
            float a1 = Xs[ty * 4 + 1][k];
            float a2 = Xs[ty * 4 + 2][k];
            float a3 = Xs[ty * 4 + 3][k];
            float4 bv = *(float4*)&Ws[k][tx * 4];
            acc[0][0] = fmaf(a0, bv.x, acc[0][0]); acc[0][1] = fmaf(a0, bv.y, acc[0][1]);
            acc[0][2] = fmaf(a0, bv.z, acc[0][2]); acc[0][3] = fmaf(a0, bv.w, acc[0][3]);
            acc[1][0] = fmaf(a1, bv.x, acc[1][0]); acc[1][1] = fmaf(a1, bv.y, acc[1][1]);
            acc[1][2] = fmaf(a1, bv.z, acc[1][2]); acc[1][3] = fmaf(a1, bv.w, acc[1][3]);
            acc[2][0] = fmaf(a2, bv.x, acc[2][0]); acc[2][1] = fmaf(a2, bv.y, acc[2][1]);
            acc[2][2] = fmaf(a2, bv.z, acc[2][2]); acc[2][3] = fmaf(a2, bv.w, acc[2][3]);
            acc[3][0] = fmaf(a3, bv.x, acc[3][0]); acc[3][1] = fmaf(a3, bv.y, acc[3][1]);
            acc[3][2] = fmaf(a3, bv.z, acc[3][2]); acc[3][3] = fmaf(a3, bv.w, acc[3][3]);
        }
        __syncthreads();
    }

    // ---- epilogue 1: attention logits from fp32 accumulators ----
    {
        const float* as = a_self  + head * F_OUT;
        const float* an = a_neigh + head * F_OUT;
        float s[4] = {}, nn[4] = {};
        #pragma unroll
        for (int r = 0; r < 4; r++) {
            #pragma unroll
            for (int c = 0; c < 4; c++) {
                s[r]  = fmaf(acc[r][c], as[tx * 4 + c], s[r]);
                nn[r] = fmaf(acc[r][c], an[tx * 4 + c], nn[r]);
            }
        }
        #pragma unroll
        for (int off = 8; off >= 1; off >>= 1) {
            #pragma unroll
            for (int r = 0; r < 4; r++) {
                s[r]  += __shfl_xor_sync(0xFFFFFFFFu, s[r], off);
                nn[r] += __shfl_xor_sync(0xFFFFFFFFu, nn[r], off);
            }
        }
        if (tx == 0) {
            #pragma unroll
            for (int r = 0; r < 4; r++) {
                size_t idx = ((size_t)b * N_ + n0 + ty * 4 + r) * H_ + head;
                g_atts2[idx] = s[r];
                g_attn2[idx] = nn[r];
            }
        }
    }

    // ---- epilogue 2: fp16 h store to [b][n][h][o] ----
    #pragma unroll
    for (int r = 0; r < 4; r++) {
        int n = n0 + ty * 4 + r;
        __half2 p0 = __floats2half2_rn(acc[r][0], acc[r][1]);
        __half2 p1 = __floats2half2_rn(acc[r][2], acc[r][3]);
        __half2* dst = (__half2*)(g_h16 + ((size_t)b * N_ + n) * HF + head * F_OUT + tx * 4);
        dst[0] = p0;
        dst[1] = p1;
    }
}

// -------------------------------------------------------------------------
// Kernel 2: CSR neighbor lists. One warp per (b,i) row.
// float4 per lane, prefetch depth 2 (MLP~2.5), 4-ballot compaction.
// Output order within a 128-col chunk is component-grouped — softmax is
// permutation-invariant, so this is safe.
// -------------------------------------------------------------------------
__global__ __launch_bounds__(256) void nbr_kernel(const float* __restrict__ A) {
    int warp = (blockIdx.x * blockDim.x + threadIdx.x) >> 5;
    int lane = threadIdx.x & 31;
    if (warp >= B_ * N_) return;
    const float* row = A + (size_t)warp * N_;
    int* outp = g_nbr + (size_t)warp * DEG_CAP;
    int base = 0;

    float4 v0 = *(const float4*)(row + lane * 4);
    float4 v1 = *(const float4*)(row + 128 + lane * 4);

    for (int c = 0; c < N_; c += 128) {
        float4 v = v0;
        v0 = v1;
        if (c + 256 < N_) v1 = *(const float4*)(row + c + 256 + lane * 4);

        unsigned mx = __ballot_sync(0xFFFFFFFFu, v.x != 0.0f);
        unsigned my = __ballot_sync(0xFFFFFFFFu, v.y != 0.0f);
        unsigned mz = __ballot_sync(0xFFFFFFFFu, v.z != 0.0f);
        unsigned mw = __ballot_sync(0xFFFFFFFFu, v.w != 0.0f);
        unsigned lt = (1u << lane) - 1u;
        int cx = __popc(mx), cy = __popc(my), cz = __popc(mz), cw = __popc(mw);
        int col = c + lane * 4;

        if (v.x != 0.0f) { int p = base + __popc(mx & lt);           if (p < DEG_CAP) outp[p] = col;     }
        if (v.y != 0.0f) { int p = base + cx + __popc(my & lt);      if (p < DEG_CAP) outp[p] = col + 1; }
        if (v.z != 0.0f) { int p = base + cx + cy + __popc(mz & lt); if (p < DEG_CAP) outp[p] = col + 2; }
        if (v.w != 0.0f) { int p = base + cx + cy + cz + __popc(mw & lt); if (p < DEG_CAP) outp[p] = col + 3; }
        base += cx + cy + cz + cw;
    }
    if (lane == 0) g_deg[warp] = base < DEG_CAP ? base : DEG_CAP;
}

// -------------------------------------------------------------------------
// Kernel 3: sparse gather-aggregate, fp16 payload (identical to R4 best).
// CTA = (b,i); warp = head. Lane l handles neighbor k+(l>>3), cols (l&7)*8.
// -------------------------------------------------------------------------
__global__ __launch_bounds__(256) void agg_kernel(float* __restrict__ out) {
    const int bi = blockIdx.x;          // b*N + i
    const int b  = bi >> 11;
    const int t  = threadIdx.x;
    const int h  = t >> 5;
    const int l  = t & 31;

    __shared__ int   idx_s[DEG_CAP];
    __shared__ float w_s[DEG_CAP][8];
    __shared__ float atts_s[8];

    const int deg  = g_deg[bi];
    const int deg4 = (deg + 3) & ~3;

    for (int k = t; k < deg; k += 256) idx_s[k] = g_nbr[(size_t)bi * DEG_CAP + k];
    if (t < 8) atts_s[t] = g_atts2[(size_t)bi * 8 + t];
    __syncthreads();

    // phase 1: weights for all (neighbor, head); pad [deg, deg4) with zeros
    if (t < deg) {
        int j = idx_s[t];
        const float* an = g_attn2 + ((size_t)(b * N_) + j) * 8;
        float4 a0 = *(const float4*)an;
        float4 a1 = *(const float4*)(an + 4);
        float vals[8] = {a0.x, a0.y, a0.z, a0.w, a1.x, a1.y, a1.z, a1.w};
        float w[8];
        #pragma unroll
        for (int hh = 0; hh < 8; hh++) {
            float x  = atts_s[hh] + vals[hh];
            float sc = fmaxf(x, 0.2f * x);
            w[hh] = __expf(sc);
        }
        *(float4*)&w_s[t][0] = make_float4(w[0], w[1], w[2], w[3]);
        *(float4*)&w_s[t][4] = make_float4(w[4], w[5], w[6], w[7]);
    } else if (t < deg4) {
        idx_s[t] = 0;
        *(float4*)&w_s[t][0] = make_float4(0.f, 0.f, 0.f, 0.f);
        *(float4*)&w_s[t][4] = make_float4(0.f, 0.f, 0.f, 0.f);
    }
    __syncthreads();

    // phase 2: gather + weighted sum. grp = l>>3 selects one of 4 neighbors.
    const int grp = l >> 3;
    const int q8  = (l & 7) * 8;     // 8 halves per lane
    const __half* hb = g_h16 + ((size_t)b * N_) * HF + h * F_OUT + q8;

    float acc[8] = {};
    float dacc = 0.f;

    for (int k = 0; k < deg4; k += 4) {
        int   j = idx_s[k + grp];
        float w = w_s[k + grp][h];
        uint4 v = *(const uint4*)(hb + (unsigned)j * HF);
        __half2 h01 = *(__half2*)&v.x;
        __half2 h23 = *(__half2*)&v.y;
        __half2 h45 = *(__half2*)&v.z;
        __half2 h67 = *(__half2*)&v.w;
        float2 f01 = __half22float2(h01);
        float2 f23 = __half22float2(h23);
        float2 f45 = __half22float2(h45);
        float2 f67 = __half22float2(h67);
        acc[0] = fmaf(w, f01.x, acc[0]); acc[1] = fmaf(w, f01.y, acc[1]);
        acc[2] = fmaf(w, f23.x, acc[2]); acc[3] = fmaf(w, f23.y, acc[3]);
        acc[4] = fmaf(w, f45.x, acc[4]); acc[5] = fmaf(w, f45.y, acc[5]);
        acc[6] = fmaf(w, f67.x, acc[6]); acc[7] = fmaf(w, f67.y, acc[7]);
        dacc += w;
    }

    // combine the 4 neighbor-groups (and the denominator) across lanes
    #pragma unroll
    for (int c = 0; c < 8; c++) {
        acc[c] += __shfl_xor_sync(0xFFFFFFFFu, acc[c], 8);
        acc[c] += __shfl_xor_sync(0xFFFFFFFFu, acc[c], 16);
    }
    dacc += __shfl_xor_sync(0xFFFFFFFFu, dacc, 8);
    dacc += __shfl_xor_sync(0xFFFFFFFFu, dacc, 16);

    if (l < 8) {
        float inv = 1.0f / dacc;
        float4 o0, o1;
        o0.x = fmaxf(acc[0] * inv, 0.f); o0.y = fmaxf(acc[1] * inv, 0.f);
        o0.z = fmaxf(acc[2] * inv, 0.f); o0.w = fmaxf(acc[3] * inv, 0.f);
        o1.x = fmaxf(acc[4] * inv, 0.f); o1.y = fmaxf(acc[5] * inv, 0.f);
        o1.z = fmaxf(acc[6] * inv, 0.f); o1.w = fmaxf(acc[7] * inv, 0.f);
        float* op = out + (size_t)bi * HF + h * F_OUT + q8;
        *(float4*)op       = o0;
        *(float4*)(op + 4) = o1;
    }
}

// -------------------------------------------------------------------------
extern "C" void kernel_launch(void* const* d_in, const int* in_sizes, int n_in,
                              void* d_out, int out_size) {
    const float* X       = (const float*)d_in[0];
    const float* A       = (const float*)d_in[1];
    const float* W       = (const float*)d_in[2];
    const float* a_self  = (const float*)d_in[3];
    const float* a_neigh = (const float*)d_in[4];
    float* out = (float*)d_out;

    // 1) adjacency -> CSR neighbor lists
    nbr_kernel<<<(B_ * N_) / 8, 256>>>(A);

    // 2) h = X @ W per head + fused att logits + fp16 h store
    gemm_h_kernel<<<dim3((N_ / 64) * B_, H_), 256>>>(X, W, a_self, a_neigh);

    // 3) sparse masked-softmax aggregation + relu + concat
    agg_kernel<<<B_ * N_, 256>>>(out);
}

// round 8
// speedup vs baseline: 1.0775x; 1.0579x over previous
#include <cuda_runtime.h>
#include <cuda_fp16.h>

#define B_    4
#define N_    2048
#define F_IN  256
#define H_    8
#define F_OUT 64
#define HF    (H_ * F_OUT)       // 512
#define DEG_CAP 256

// Scratch (device globals: allocation-free per harness rules)
__device__ __half g_h16[(size_t)B_ * N_ * HF];     // [b][n][h][o], fp16
__device__ float  g_atts2[B_ * N_ * H_];           // [b][n][h]
__device__ float  g_attn2[B_ * N_ * H_];           // [b][n][h]

// -------------------------------------------------------------------------
// Kernel 1: h = X @ W per head (fp32 accum), 64x64 tile, 4x4 micro-tile.
// Fused epilogue: att logits from fp32 accs (exact) + fp16 h store [b][n][h][o].
// (identical to R4 measured-best)
// -------------------------------------------------------------------------
__global__ __launch_bounds__(256) void gemm_h_kernel(const float* __restrict__ X,
                                                     const float* __restrict__ W,
                                                     const float* __restrict__ a_self,
                                                     const float* __restrict__ a_neigh) {
    const int head = blockIdx.y;
    const int b    = blockIdx.x >> 5;
    const int n0   = (blockIdx.x & 31) * 64;

    __shared__ float Xs[64][20];
    __shared__ float Ws[16][64];

    const int t  = threadIdx.x;
    const int ty = t >> 4;
    const int tx = t & 15;

    const float* Xb = X + ((size_t)b * N_ + n0) * F_IN;
    const float* Wh = W + (size_t)head * F_IN * F_OUT;

    float acc[4][4] = {};

    for (int k0 = 0; k0 < F_IN; k0 += 16) {
        {
            int row = t >> 2;
            int q   = (t & 3) * 4;
            float4 v = *(const float4*)(Xb + (size_t)row * F_IN + k0 + q);
            *(float4*)&Xs[row][q] = v;
        }
        {
            int r = t >> 4;
            int q = (t & 15) * 4;
            *(float4*)&Ws[r][q] = *(const float4*)(Wh + (size_t)(k0 + r) * F_OUT + q);
        }
        __syncthreads();

        #pragma unroll
        for (int k = 0; k < 16; k++) {
            float a0 = Xs[ty * 4 + 0][k];
            float a1 = Xs[ty * 4 + 1][k];
            float a2 = Xs[ty * 4 + 2][k];
            float a3 = Xs[ty * 4 + 3][k];
            float4 bv = *(float4*)&Ws[k][tx * 4];
            acc[0][0] = fmaf(a0, bv.x, acc[0][0]); acc[0][1] = fmaf(a0, bv.y, acc[0][1]);
            acc[0][2] = fmaf(a0, bv.z, acc[0][2]); acc[0][3] = fmaf(a0, bv.w, acc[0][3]);
            acc[1][0] = fmaf(a1, bv.x, acc[1][0]); acc[1][1] = fmaf(a1, bv.y, acc[1][1]);
            acc[1][2] = fmaf(a1, bv.z, acc[1][2]); acc[1][3] = fmaf(a1, bv.w, acc[1][3]);
            acc[2][0] = fmaf(a2, bv.x, acc[2][0]); acc[2][1] = fmaf(a2, bv.y, acc[2][1]);
            acc[2][2] = fmaf(a2, bv.z, acc[2][2]); acc[2][3] = fmaf(a2, bv.w, acc[2][3]);
            acc[3][0] = fmaf(a3, bv.x, acc[3][0]); acc[3][1] = fmaf(a3, bv.y, acc[3][1]);
            acc[3][2] = fmaf(a3, bv.z, acc[3][2]); acc[3][3] = fmaf(a3, bv.w, acc[3][3]);
        }
        __syncthreads();
    }

    // ---- epilogue 1: attention logits from fp32 accumulators ----
    {
        const float* as = a_self  + head * F_OUT;
        const float* an = a_neigh + head * F_OUT;
        float s[4] = {}, nn[4] = {};
        #pragma unroll
        for (int r = 0; r < 4; r++) {
            #pragma unroll
            for (int c = 0; c < 4; c++) {
                s[r]  = fmaf(acc[r][c], as[tx * 4 + c], s[r]);
                nn[r] = fmaf(acc[r][c], an[tx * 4 + c], nn[r]);
            }
        }
        #pragma unroll
        for (int off = 8; off >= 1; off >>= 1) {
            #pragma unroll
            for (int r = 0; r < 4; r++) {
                s[r]  += __shfl_xor_sync(0xFFFFFFFFu, s[r], off);
                nn[r] += __shfl_xor_sync(0xFFFFFFFFu, nn[r], off);
            }
        }
        if (tx == 0) {
            #pragma unroll
            for (int r = 0; r < 4; r++) {
                size_t idx = ((size_t)b * N_ + n0 + ty * 4 + r) * H_ + head;
                g_atts2[idx] = s[r];
                g_attn2[idx] = nn[r];
            }
        }
    }

    // ---- epilogue 2: fp16 h store to [b][n][h][o] ----
    #pragma unroll
    for (int r = 0; r < 4; r++) {
        int n = n0 + ty * 4 + r;
        __half2 p0 = __floats2half2_rn(acc[r][0], acc[r][1]);
        __half2 p1 = __floats2half2_rn(acc[r][2], acc[r][3]);
        __half2* dst = (__half2*)(g_h16 + ((size_t)b * N_ + n) * HF + head * F_OUT + tx * 4);
        dst[0] = p0;
        dst[1] = p1;
    }
}

// -------------------------------------------------------------------------
// Kernel 2: fused A-row compaction + sparse gather-aggregate.
// CTA = (b,i); 8 warps. Phase 0 compacts this row's adjacency into smem
// (warp w covers cols [w*256, w*256+256)). Then warp = head for the gather.
// Neighbor order is warp-segmented — softmax is permutation-invariant.
// -------------------------------------------------------------------------
__global__ __launch_bounds__(256) void agg_kernel(const float* __restrict__ A,
                                                  float* __restrict__ out) {
    const int bi = blockIdx.x;          // b*N + i
    const int b  = bi >> 11;
    const int t  = threadIdx.x;
    const int h  = t >> 5;              // warp id == head in gather phases
    const int l  = t & 31;

    __shared__ int   idx_s[DEG_CAP];
    __shared__ float w_s[DEG_CAP][8];
    __shared__ float atts_s[8];
    __shared__ int   wcnt[8];

    // ---- phase 0: compact adjacency row into idx_s ----
    {
        const float* Arow = A + (size_t)bi * N_;
        const int base_col = h * 256 + l * 8;
        float4 va = *(const float4*)(Arow + base_col);
        float4 vb = *(const float4*)(Arow + base_col + 4);
        unsigned m8 = (va.x != 0.0f ? 1u   : 0u) | (va.y != 0.0f ? 2u   : 0u) |
                      (va.z != 0.0f ? 4u   : 0u) | (va.w != 0.0f ? 8u   : 0u) |
                      (vb.x != 0.0f ? 16u  : 0u) | (vb.y != 0.0f ? 32u  : 0u) |
                      (vb.z != 0.0f ? 64u  : 0u) | (vb.w != 0.0f ? 128u : 0u);
        int cnt  = __popc(m8);
        int incl = cnt;
        #pragma unroll
        for (int off = 1; off < 32; off <<= 1) {
            int o = __shfl_up_sync(0xFFFFFFFFu, incl, off);
            if (l >= off) incl += o;
        }
        if (l == 31) wcnt[h] = incl;           // warp total
        int excl = incl - cnt;
        __syncthreads();

        int woff = 0;
        #pragma unroll
        for (int ww = 0; ww < 8; ww++) if (ww < h) woff += wcnt[ww];

        int pos = woff + excl;
        unsigned mm = m8;
        while (mm) {
            int bit = __ffs(mm) - 1;
            mm &= mm - 1u;
            if (pos < DEG_CAP) idx_s[pos] = base_col + bit;
            pos++;
        }
    }
    if (t < 8) atts_s[t] = g_atts2[(size_t)bi * 8 + t];
    __syncthreads();

    int deg = wcnt[0] + wcnt[1] + wcnt[2] + wcnt[3] +
              wcnt[4] + wcnt[5] + wcnt[6] + wcnt[7];
    deg = deg < DEG_CAP ? deg : DEG_CAP;
    const int deg4 = (deg + 3) & ~3;

    // ---- phase 1: weights for all (neighbor, head); pad [deg, deg4) ----
    if (t < deg) {
        int j = idx_s[t];
        const float* an = g_attn2 + ((size_t)(b * N_) + j) * 8;
        float4 a0 = *(const float4*)an;
        float4 a1 = *(const float4*)(an + 4);
        float vals[8] = {a0.x, a0.y, a0.z, a0.w, a1.x, a1.y, a1.z, a1.w};
        float w[8];
        #pragma unroll
        for (int hh = 0; hh < 8; hh++) {
            float x  = atts_s[hh] + vals[hh];
            float sc = fmaxf(x, 0.2f * x);
            w[hh] = __expf(sc);
        }
        *(float4*)&w_s[t][0] = make_float4(w[0], w[1], w[2], w[3]);
        *(float4*)&w_s[t][4] = make_float4(w[4], w[5], w[6], w[7]);
    } else if (t < deg4) {
        idx_s[t] = 0;
        *(float4*)&w_s[t][0] = make_float4(0.f, 0.f, 0.f, 0.f);
        *(float4*)&w_s[t][4] = make_float4(0.f, 0.f, 0.f, 0.f);
    }
    __syncthreads();

    // ---- phase 2: gather + weighted sum. grp = l>>3 picks 1 of 4 nbrs ----
    const int grp = l >> 3;
    const int q8  = (l & 7) * 8;     // 8 halves per lane
    const __half* hb = g_h16 + ((size_t)b * N_) * HF + h * F_OUT + q8;

    float acc[8] = {};
    float dacc = 0.f;

    for (int k = 0; k < deg4; k += 4) {
        int   j = idx_s[k + grp];
        float w = w_s[k + grp][h];
        uint4 v = *(const uint4*)(hb + (unsigned)j * HF);
        float2 f01 = __half22float2(*(__half2*)&v.x);
        float2 f23 = __half22float2(*(__half2*)&v.y);
        float2 f45 = __half22float2(*(__half2*)&v.z);
        float2 f67 = __half22float2(*(__half2*)&v.w);
        acc[0] = fmaf(w, f01.x, acc[0]); acc[1] = fmaf(w, f01.y, acc[1]);
        acc[2] = fmaf(w, f23.x, acc[2]); acc[3] = fmaf(w, f23.y, acc[3]);
        acc[4] = fmaf(w, f45.x, acc[4]); acc[5] = fmaf(w, f45.y, acc[5]);
        acc[6] = fmaf(w, f67.x, acc[6]); acc[7] = fmaf(w, f67.y, acc[7]);
        dacc += w;
    }

    // combine the 4 neighbor-groups (and the denominator) across lanes
    #pragma unroll
    for (int c = 0; c < 8; c++) {
        acc[c] += __shfl_xor_sync(0xFFFFFFFFu, acc[c], 8);
        acc[c] += __shfl_xor_sync(0xFFFFFFFFu, acc[c], 16);
    }
    dacc += __shfl_xor_sync(0xFFFFFFFFu, dacc, 8);
    dacc += __shfl_xor_sync(0xFFFFFFFFu, dacc, 16);

    if (l < 8) {
        float inv = 1.0f / dacc;
        float4 o0, o1;
        o0.x = fmaxf(acc[0] * inv, 0.f); o0.y = fmaxf(acc[1] * inv, 0.f);
        o0.z = fmaxf(acc[2] * inv, 0.f); o0.w = fmaxf(acc[3] * inv, 0.f);
        o1.x = fmaxf(acc[4] * inv, 0.f); o1.y = fmaxf(acc[5] * inv, 0.f);
        o1.z = fmaxf(acc[6] * inv, 0.f); o1.w = fmaxf(acc[7] * inv, 0.f);
        float* op = out + (size_t)bi * HF + h * F_OUT + q8;
        *(float4*)op       = o0;
        *(float4*)(op + 4) = o1;
    }
}

// -------------------------------------------------------------------------
extern "C" void kernel_launch(void* const* d_in, const int* in_sizes, int n_in,
                              void* d_out, int out_size) {
    const float* X       = (const float*)d_in[0];
    const float* A       = (const float*)d_in[1];
    const float* W       = (const float*)d_in[2];
    const float* a_self  = (const float*)d_in[3];
    const float* a_neigh = (const float*)d_in[4];
    float* out = (float*)d_out;

    // 1) h = X @ W per head + fused att logits + fp16 h store
    gemm_h_kernel<<<dim3((N_ / 64) * B_, H_), 256>>>(X, W, a_self, a_neigh);

    // 2) fused adjacency compaction + sparse softmax aggregation + relu + concat
    agg_kernel<<<B_ * N_, 256>>>(A, out);
}